// round 1
// baseline (speedup 1.0000x reference)
#include <cuda_runtime.h>

#define BB 4
#define CCH 64
#define HH 256
#define WWD 256
#define HWW (HH*WWD)
#define NHEADS 4
#define DDIM 16
#define WHF 128
#define NSQ (HH*WHF)
#define C2 128
#define C4 256

// ---------------- scratch (static device allocations only) ----------------
__device__ float g_q1[BB*CCH*HWW];
__device__ float g_k1[BB*CCH*HWW];
__device__ float g_v1[BB*CCH*HWW];
__device__ float g_qs[BB*CCH*NSQ];
__device__ float g_ks[BB*CCH*NSQ];
__device__ float g_vs[BB*CCH*NSQ];
__device__ float g_ctx[BB*NHEADS*DDIM*DDIM];
__device__ float g_att[BB*CCH*HWW];
__device__ float g_attn[BB*C2*HWW];
__device__ float g_m1[BB*C4*HWW];
__device__ float g_m2[BB*C4*HWW];

__device__ __forceinline__ float gelu_f(float x) {
    return 0.5f * x * (1.0f + erff(x * 0.7071067811865476f));
}

// ---------------- 1x1 conv as tiled GEMM ----------------
// tile: 64 co x 128 px, K-chunks of 32. thread: 4 co x 8 px (two 4-px groups 64 apart).
// ACT: 0 none, 1 gelu, 2 add-residual. MASK: 0 none, 1 keep (i+j)%2==0, 2 keep ==1.
template<int CIN, int COUT, int ACT, int MASK>
__global__ __launch_bounds__(256) void conv1x1_kernel(
    const float* __restrict__ in, const float* __restrict__ wt,
    const float* __restrict__ bias, const float* __restrict__ res,
    float* __restrict__ out)
{
    __shared__ float Ws[32][65];    // [ci][co], pad 65 -> conflict-free transpose store
    __shared__ float Xs[32][128];   // [ci][px]

    const int p0  = blockIdx.x * 128;
    const int cot = blockIdx.y;
    const int b   = blockIdx.z;
    const int tid = threadIdx.x;

    const int px0 = (tid & 15) * 4;   // 4 px + 4 px at +64
    const int co0 = (tid >> 4) * 4;

    float acc[4][8];
    #pragma unroll
    for (int u = 0; u < 4; u++)
        #pragma unroll
        for (int v = 0; v < 8; v++) acc[u][v] = 0.f;

    for (int k0 = 0; k0 < CIN; k0 += 32) {
        __syncthreads();
        // weights: rows ci, cols co (transposed store, conflict-free via pad)
        #pragma unroll
        for (int q = tid; q < 2048; q += 256) {
            int co = q >> 5;
            int ci = q & 31;
            Ws[ci][co] = wt[(size_t)(cot*64 + co) * CIN + k0 + ci];
        }
        // X tile, float4 coalesced
        #pragma unroll
        for (int q = tid; q < 1024; q += 256) {
            int ci = q >> 5;
            int f4 = q & 31;
            int p  = p0 + f4 * 4;
            float4 v = *reinterpret_cast<const float4*>(
                in + (size_t)(b * CIN + k0 + ci) * HWW + p);
            if (MASK) {
                int i  = p >> 8;
                int j  = p & 255;
                int pb = (i + j) & 1;
                int kp = (MASK == 1) ? pb : (pb ^ 1); // keep components with u-parity == kp
                if (kp == 0) { v.y = 0.f; v.w = 0.f; }
                else         { v.x = 0.f; v.z = 0.f; }
            }
            *reinterpret_cast<float4*>(&Xs[ci][f4*4]) = v;
        }
        __syncthreads();

        #pragma unroll
        for (int k = 0; k < 32; k++) {
            float av[4];
            #pragma unroll
            for (int u = 0; u < 4; u++) av[u] = Ws[k][co0 + u];
            float4 b0 = *reinterpret_cast<const float4*>(&Xs[k][px0]);
            float4 b1 = *reinterpret_cast<const float4*>(&Xs[k][px0 + 64]);
            float bv[8] = {b0.x,b0.y,b0.z,b0.w,b1.x,b1.y,b1.z,b1.w};
            #pragma unroll
            for (int u = 0; u < 4; u++)
                #pragma unroll
                for (int v = 0; v < 8; v++)
                    acc[u][v] += av[u] * bv[v];
        }
    }

    #pragma unroll
    for (int u = 0; u < 4; u++) {
        int co = cot*64 + co0 + u;
        float bb = bias[co];
        size_t base = (size_t)(b * COUT + co) * HWW + p0;
        #pragma unroll
        for (int g = 0; g < 2; g++) {
            size_t off = base + px0 + g * 64;
            float4 o;
            float* ov = reinterpret_cast<float*>(&o);
            #pragma unroll
            for (int v = 0; v < 4; v++) {
                float val = acc[u][g*4 + v] + bb;
                if (ACT == 1) val = gelu_f(val);
                if (ACT == 2) val += res[off + v];
                ov[v] = val;
            }
            *reinterpret_cast<float4*>(out + off) = o;
        }
    }
}

// ---------------- depthwise 3x3 fused with checkerboard squeeze ----------------
// anchor=0: out[i][j] = dw(in)[i][2j + (i&1)]   (nonanchor squeeze, for q)
// anchor=1: out[i][j] = dw(in)[i][2j + 1-(i&1)] (anchor squeeze, for k/v)
__global__ void dw_squeeze_kernel(const float* __restrict__ in,
                                  const float* __restrict__ wt,
                                  const float* __restrict__ bias,
                                  float* __restrict__ out, int anchor)
{
    int id = blockIdx.x * blockDim.x + threadIdx.x;
    if (id >= BB*CCH*NSQ) return;
    int j = id & (WHF-1);
    int i = (id >> 7) & (HH-1);
    int c = (id >> 15) & (CCH-1);
    int b = id >> 21;
    int x = 2*j + (anchor ? (1 - (i & 1)) : (i & 1));
    float w[9];
    #pragma unroll
    for (int t = 0; t < 9; t++) w[t] = __ldg(&wt[c*9 + t]);
    float acc = bias[c];
    const float* base = in + (size_t)(b*CCH + c) * HWW;
    #pragma unroll
    for (int dy = -1; dy <= 1; dy++) {
        int yy = i + dy;
        if (yy < 0 || yy >= HH) continue;
        #pragma unroll
        for (int dx = -1; dx <= 1; dx++) {
            int xx = x + dx;
            if (xx < 0 || xx >= WWD) continue;
            acc += w[(dy+1)*3 + (dx+1)] * base[yy*WWD + xx];
        }
    }
    out[id] = acc;
}

// ---------------- softmax over n per (b,c) row, in place ----------------
__global__ __launch_bounds__(512) void softmax_k_kernel(float* __restrict__ data)
{
    __shared__ float sm[16];
    float* ptr = data + (size_t)blockIdx.x * NSQ;
    int tid = threadIdx.x;

    float m = -1e30f;
    for (int idx = tid; idx < NSQ; idx += 512) m = fmaxf(m, ptr[idx]);
    #pragma unroll
    for (int o = 16; o; o >>= 1) m = fmaxf(m, __shfl_xor_sync(0xffffffffu, m, o));
    if ((tid & 31) == 0) sm[tid >> 5] = m;
    __syncthreads();
    if (tid < 32) {
        float t = (tid < 16) ? sm[tid] : -1e30f;
        #pragma unroll
        for (int o = 8; o; o >>= 1) t = fmaxf(t, __shfl_xor_sync(0xffffffffu, t, o));
        if (tid == 0) sm[0] = t;
    }
    __syncthreads();
    m = sm[0];
    __syncthreads();

    float s = 0.f;
    for (int idx = tid; idx < NSQ; idx += 512) s += expf(ptr[idx] - m);
    #pragma unroll
    for (int o = 16; o; o >>= 1) s += __shfl_xor_sync(0xffffffffu, s, o);
    if ((tid & 31) == 0) sm[tid >> 5] = s;
    __syncthreads();
    if (tid < 32) {
        float t = (tid < 16) ? sm[tid] : 0.f;
        #pragma unroll
        for (int o = 8; o; o >>= 1) t += __shfl_xor_sync(0xffffffffu, t, o);
        if (tid == 0) sm[0] = t;
    }
    __syncthreads();
    float inv = 1.f / sm[0];
    for (int idx = tid; idx < NSQ; idx += 512) ptr[idx] = expf(ptr[idx] - m) * inv;
}

// ---------------- ctx = k_sm @ v_s^T  (16x16 per (b,head)) ----------------
__global__ void ctx_zero_kernel() {
    int id = blockIdx.x * blockDim.x + threadIdx.x;
    if (id < BB*NHEADS*DDIM*DDIM) g_ctx[id] = 0.f;
}

__global__ __launch_bounds__(256) void ctx_kernel()
{
    __shared__ float ka[16][129];
    __shared__ float va[16][129];
    int bh = blockIdx.x;
    int chunk = blockIdx.y;            // 32 chunks x 1024 n
    int b = bh >> 2, h = bh & 3;
    int tid = threadIdx.x;
    int d = tid >> 4, e = tid & 15;
    const float* kbase = g_ks + (size_t)(b*CCH + h*16) * NSQ;
    const float* vbase = g_vs + (size_t)(b*CCH + h*16) * NSQ;
    float acc = 0.f;
    for (int sub = 0; sub < 8; sub++) {
        int n0 = chunk * 1024 + sub * 128;
        __syncthreads();
        #pragma unroll
        for (int q = tid; q < 2048; q += 256) {
            int r = q >> 7, t = q & 127;
            ka[r][t] = kbase[(size_t)r * NSQ + n0 + t];
            va[r][t] = vbase[(size_t)r * NSQ + n0 + t];
        }
        __syncthreads();
        #pragma unroll
        for (int t = 0; t < 128; t++) acc += ka[d][t] * va[e][t];
    }
    atomicAdd(&g_ctx[bh*256 + tid], acc);
}

// ---------------- q softmax(over d) + ctx apply + nonanchor unsqueeze ----------------
__global__ __launch_bounds__(256) void att_kernel()
{
    __shared__ float cs[16][17];
    int bh = blockIdx.y;
    int b = bh >> 2, h = bh & 3;
    int tid = threadIdx.x;
    int n = blockIdx.x * 256 + tid;
    cs[tid >> 4][tid & 15] = g_ctx[bh*256 + tid];
    __syncthreads();

    const float* qb = g_qs + (size_t)(b*CCH + h*16) * NSQ + n;
    float p[16];
    float m = -1e30f;
    #pragma unroll
    for (int d = 0; d < 16; d++) { p[d] = qb[(size_t)d * NSQ]; m = fmaxf(m, p[d]); }
    float s = 0.f;
    #pragma unroll
    for (int d = 0; d < 16; d++) { p[d] = expf(p[d] - m); s += p[d]; }
    float inv = 1.f / s;

    int i = n >> 7, j = n & 127;
    int xa = 2*j + (i & 1);   // value position (nonanchor)
    int xo = xa ^ 1;          // zero position
    #pragma unroll
    for (int e = 0; e < 16; e++) {
        float a = 0.f;
        #pragma unroll
        for (int d = 0; d < 16; d++) a += cs[d][e] * p[d];
        a *= inv;
        size_t base = ((size_t)(b*CCH + h*16 + e) * HH + i) * WWD;
        g_att[base + xa] = a;
        g_att[base + xo] = 0.f;
    }
}

// ---------------- 5x5 conv 64 -> 128, pad 2 ----------------
// block: 16 co x (128 x 4) px; thread: 4 co x 8 px; smem input halo + [co][tap] weights
__global__ __launch_bounds__(256) void conv5_kernel(
    const float* __restrict__ wt, const float* __restrict__ bias)
{
    __shared__ float xs[8][132];
    __shared__ float ws[16][26];
    int x0  = blockIdx.x * 128;
    int y0  = blockIdx.y * 4;
    int b   = blockIdx.z >> 3;
    int cot = blockIdx.z & 7;
    int tid = threadIdx.x;
    int cg  = tid >> 6;            // 0..3 -> 4 co each
    int pg  = tid & 63;
    int py  = pg >> 4;             // 0..3
    int px0 = (pg & 15) * 8;       // 0..120

    float acc[4][8];
    #pragma unroll
    for (int u = 0; u < 4; u++)
        #pragma unroll
        for (int v = 0; v < 8; v++) acc[u][v] = 0.f;

    for (int ci = 0; ci < 64; ci++) {
        __syncthreads();
        const float* ib = g_att + (size_t)(b*CCH + ci) * HWW;
        for (int q = tid; q < 1056; q += 256) {
            int r = q / 132, cc = q - r * 132;
            int gy = y0 + r - 2, gx = x0 + cc - 2;
            float v = 0.f;
            if (gy >= 0 && gy < HH && gx >= 0 && gx < WWD) v = ib[gy*WWD + gx];
            xs[r][cc] = v;
        }
        for (int q = tid; q < 400; q += 256) {
            int co = q / 25, tap = q - co * 25;
            ws[co][tap] = wt[((size_t)(cot*16 + co) * 64 + ci) * 25 + tap];
        }
        __syncthreads();

        #pragma unroll
        for (int dy = 0; dy < 5; dy++) {
            float4 v0 = *reinterpret_cast<const float4*>(&xs[py+dy][px0]);
            float4 v1 = *reinterpret_cast<const float4*>(&xs[py+dy][px0+4]);
            float4 v2 = *reinterpret_cast<const float4*>(&xs[py+dy][px0+8]);
            float xv[12] = {v0.x,v0.y,v0.z,v0.w, v1.x,v1.y,v1.z,v1.w, v2.x,v2.y,v2.z,v2.w};
            #pragma unroll
            for (int dx = 0; dx < 5; dx++) {
                #pragma unroll
                for (int u = 0; u < 4; u++) {
                    float w = ws[cg*4 + u][dy*5 + dx];
                    #pragma unroll
                    for (int v = 0; v < 8; v++)
                        acc[u][v] += w * xv[dx + v];
                }
            }
        }
    }

    #pragma unroll
    for (int u = 0; u < 4; u++) {
        int co = cot*16 + cg*4 + u;
        float bb = bias[co];
        size_t base = ((size_t)(b*C2 + co) * HH + (y0 + py)) * WWD + x0 + px0;
        #pragma unroll
        for (int g = 0; g < 2; g++) {
            float4 o;
            o.x = acc[u][g*4+0] + bb;
            o.y = acc[u][g*4+1] + bb;
            o.z = acc[u][g*4+2] + bb;
            o.w = acc[u][g*4+3] + bb;
            *reinterpret_cast<float4*>(&g_attn[base + g*4]) = o;
        }
    }
}

// ---------------- depthwise 3x3 (256 ch) + gelu ----------------
__global__ void dw_gelu_kernel(const float* __restrict__ in,
                               const float* __restrict__ wt,
                               const float* __restrict__ bias,
                               float* __restrict__ out)
{
    int id = blockIdx.x * blockDim.x + threadIdx.x;
    if (id >= BB*C4*HWW) return;
    int j = id & 255;
    int i = (id >> 8) & 255;
    int c = (id >> 16) & 255;
    int b = id >> 24;
    float w[9];
    #pragma unroll
    for (int t = 0; t < 9; t++) w[t] = __ldg(&wt[c*9 + t]);
    float acc = bias[c];
    const float* base = in + (size_t)(b*C4 + c) * HWW;
    #pragma unroll
    for (int dy = -1; dy <= 1; dy++) {
        int yy = i + dy;
        if (yy < 0 || yy >= HH) continue;
        #pragma unroll
        for (int dx = -1; dx <= 1; dx++) {
            int xx = j + dx;
            if (xx < 0 || xx >= WWD) continue;
            acc += w[(dy+1)*3 + (dx+1)] * base[yy*WWD + xx];
        }
    }
    out[id] = gelu_f(acc);
}

// ---------------- launch ----------------
extern "C" void kernel_launch(void* const* d_in, const int* in_sizes, int n_in,
                              void* d_out, int out_size)
{
    const float* x1   = (const float*)d_in[0];
    const float* x2   = (const float*)d_in[1];
    const float* q1_w = (const float*)d_in[2];
    const float* q1_b = (const float*)d_in[3];
    const float* q2_w = (const float*)d_in[4];
    const float* q2_b = (const float*)d_in[5];
    const float* k1_w = (const float*)d_in[6];
    const float* k1_b = (const float*)d_in[7];
    const float* k2_w = (const float*)d_in[8];
    const float* k2_b = (const float*)d_in[9];
    const float* v1_w = (const float*)d_in[10];
    const float* v1_b = (const float*)d_in[11];
    const float* v2_w = (const float*)d_in[12];
    const float* v2_b = (const float*)d_in[13];
    const float* r_w  = (const float*)d_in[14];
    const float* r_b  = (const float*)d_in[15];
    const float* m1_w = (const float*)d_in[16];
    const float* m1_b = (const float*)d_in[17];
    const float* m2_w = (const float*)d_in[18];
    const float* m2_b = (const float*)d_in[19];
    const float* m3_w = (const float*)d_in[20];
    const float* m3_b = (const float*)d_in[21];
    float* out = (float*)d_out;

    float *p_q1, *p_k1, *p_v1, *p_qs, *p_ks, *p_vs, *p_attn, *p_m1, *p_m2;
    cudaGetSymbolAddress((void**)&p_q1, g_q1);
    cudaGetSymbolAddress((void**)&p_k1, g_k1);
    cudaGetSymbolAddress((void**)&p_v1, g_v1);
    cudaGetSymbolAddress((void**)&p_qs, g_qs);
    cudaGetSymbolAddress((void**)&p_ks, g_ks);
    cudaGetSymbolAddress((void**)&p_vs, g_vs);
    cudaGetSymbolAddress((void**)&p_attn, g_attn);
    cudaGetSymbolAddress((void**)&p_m1, g_m1);
    cudaGetSymbolAddress((void**)&p_m2, g_m2);

    dim3 g1(HWW/128, 1, BB);
    conv1x1_kernel<64,64,0,1><<<g1, 256>>>(x1, q1_w, q1_b, nullptr, p_q1); // q: nonanchor mask
    conv1x1_kernel<64,64,0,2><<<g1, 256>>>(x1, k1_w, k1_b, nullptr, p_k1); // k: anchor mask
    conv1x1_kernel<64,64,0,0><<<g1, 256>>>(x2, v1_w, v1_b, nullptr, p_v1); // v: no mask

    int ndw = BB*CCH*NSQ;
    dw_squeeze_kernel<<<ndw/256, 256>>>(p_q1, q2_w, q2_b, p_qs, 0);
    dw_squeeze_kernel<<<ndw/256, 256>>>(p_k1, k2_w, k2_b, p_ks, 1);
    dw_squeeze_kernel<<<ndw/256, 256>>>(p_v1, v2_w, v2_b, p_vs, 1);

    softmax_k_kernel<<<BB*CCH, 512>>>(p_ks);

    ctx_zero_kernel<<<16, 256>>>();
    ctx_kernel<<<dim3(BB*NHEADS, 32), 256>>>();

    att_kernel<<<dim3(NSQ/256, BB*NHEADS), 256>>>();

    conv5_kernel<<<dim3(2, 64, 32), 256>>>(r_w, r_b);

    conv1x1_kernel<128,256,1,0><<<dim3(HWW/128, 4, BB), 256>>>(p_attn, m1_w, m1_b, nullptr, p_m1);

    dw_gelu_kernel<<<(BB*C4*HWW)/256, 256>>>(p_m1, m2_w, m2_b, p_m2);

    conv1x1_kernel<256,128,2,0><<<dim3(HWW/128, 2, BB), 256>>>(p_m2, m3_w, m3_b, p_attn, out);
}

// round 2
// speedup vs baseline: 1.0262x; 1.0262x over previous
#include <cuda_runtime.h>

#define BB 4
#define CCH 64
#define HH 256
#define WWD 256
#define HWW (HH*WWD)
#define NHEADS 4
#define DDIM 16
#define WHF 128
#define NSQ (HH*WHF)
#define C2 128
#define C4 256

typedef unsigned long long u64;

// ---------------- scratch (static device allocations only) ----------------
__device__ float g_q1[BB*CCH*HWW];
__device__ float g_k1[BB*CCH*HWW];
__device__ float g_v1[BB*CCH*HWW];
__device__ float g_qs[BB*CCH*NSQ];
__device__ float g_ks[BB*CCH*NSQ];
__device__ float g_vs[BB*CCH*NSQ];
__device__ float g_ctx[BB*NHEADS*DDIM*DDIM];
__device__ float g_att[BB*CCH*NSQ];      // squeezed att (b, C, H, W/2)
__device__ float g_attn[BB*C2*HWW];
__device__ float g_m1[BB*C4*HWW];
__device__ float g_m2[BB*C4*HWW];

__device__ __forceinline__ float gelu_f(float x) {
    return 0.5f * x * (1.0f + erff(x * 0.7071067811865476f));
}

// ---- packed f32x2 helpers ----
__device__ __forceinline__ void fma2(u64& d, u64 a, u64 b) {
    asm("fma.rn.f32x2 %0, %1, %2, %0;" : "+l"(d) : "l"(a), "l"(b));
}
__device__ __forceinline__ u64 pk(float lo, float hi) {
    u64 r;
    asm("mov.b64 %0, {%1, %2};" : "=l"(r)
        : "r"(__float_as_uint(lo)), "r"(__float_as_uint(hi)));
    return r;
}
__device__ __forceinline__ float2 upk(u64 v) {
    unsigned int a, b;
    asm("mov.b64 {%0, %1}, %2;" : "=r"(a), "=r"(b) : "l"(v));
    return make_float2(__uint_as_float(a), __uint_as_float(b));
}

// ---------------- 1x1 conv as tiled GEMM (f32x2 packed) ----------------
// tile: 64 co x 128 px, K-chunks of 32. thread: 4 co x 8 px (two 4-px groups 64 apart).
// ACT: 0 none, 1 gelu, 2 add-residual. MASK: 0 none, 1 keep (i+j)%2==0, 2 keep ==1.
template<int CIN, int COUT, int ACT, int MASK>
__global__ __launch_bounds__(256) void conv1x1_kernel(
    const float* __restrict__ in, const float* __restrict__ wt,
    const float* __restrict__ bias, const float* __restrict__ res,
    float* __restrict__ out)
{
    __shared__ float2 Wsd[32*64];   // [ci][co], weight duplicated (w,w)
    __shared__ float  Xs[32][128];  // [ci][px]

    const int p0  = blockIdx.x * 128;
    const int cot = blockIdx.y;
    const int b   = blockIdx.z;
    const int tid = threadIdx.x;

    const int px0 = (tid & 15) * 4;   // 4 px + 4 px at +64
    const int co0 = (tid >> 4) * 4;

    u64 acc2[4][4];
    #pragma unroll
    for (int u = 0; u < 4; u++)
        #pragma unroll
        for (int v = 0; v < 4; v++) acc2[u][v] = 0ull;

    for (int k0 = 0; k0 < CIN; k0 += 32) {
        __syncthreads();
        // weights duplicated: consecutive threads -> consecutive co (conflict-free STS.64)
        #pragma unroll
        for (int q = tid; q < 2048; q += 256) {
            int co = q & 63;
            int ci = q >> 6;
            float wv = wt[(size_t)(cot*64 + co) * CIN + k0 + ci];
            Wsd[ci*64 + co] = make_float2(wv, wv);
        }
        // X tile, float4 coalesced
        #pragma unroll
        for (int q = tid; q < 1024; q += 256) {
            int ci = q >> 5;
            int f4 = q & 31;
            int p  = p0 + f4 * 4;
            float4 v = *reinterpret_cast<const float4*>(
                in + (size_t)(b * CIN + k0 + ci) * HWW + p);
            if (MASK) {
                int i  = p >> 8;
                int j  = p & 255;
                int pb = (i + j) & 1;
                int kp = (MASK == 1) ? pb : (pb ^ 1);
                if (kp == 0) { v.y = 0.f; v.w = 0.f; }
                else         { v.x = 0.f; v.z = 0.f; }
            }
            *reinterpret_cast<float4*>(&Xs[ci][f4*4]) = v;
        }
        __syncthreads();

        #pragma unroll
        for (int k = 0; k < 32; k++) {
            u64 xp0 = *reinterpret_cast<const u64*>(&Xs[k][px0]);
            u64 xp1 = *reinterpret_cast<const u64*>(&Xs[k][px0 + 2]);
            u64 xp2 = *reinterpret_cast<const u64*>(&Xs[k][px0 + 64]);
            u64 xp3 = *reinterpret_cast<const u64*>(&Xs[k][px0 + 66]);
            #pragma unroll
            for (int u = 0; u < 4; u++) {
                u64 wd = *reinterpret_cast<const u64*>(&Wsd[k*64 + co0 + u]);
                fma2(acc2[u][0], wd, xp0);
                fma2(acc2[u][1], wd, xp1);
                fma2(acc2[u][2], wd, xp2);
                fma2(acc2[u][3], wd, xp3);
            }
        }
    }

    #pragma unroll
    for (int u = 0; u < 4; u++) {
        int co = cot*64 + co0 + u;
        float bb = bias[co];
        size_t base = (size_t)(b * COUT + co) * HWW + p0;
        #pragma unroll
        for (int g = 0; g < 2; g++) {
            size_t off = base + px0 + g * 64;
            float2 pa = upk(acc2[u][g*2 + 0]);
            float2 pb = upk(acc2[u][g*2 + 1]);
            float vals[4] = {pa.x, pa.y, pb.x, pb.y};
            float4 o;
            float* ov = reinterpret_cast<float*>(&o);
            #pragma unroll
            for (int v = 0; v < 4; v++) {
                float val = vals[v] + bb;
                if (ACT == 1) val = gelu_f(val);
                if (ACT == 2) val += res[off + v];
                ov[v] = val;
            }
            *reinterpret_cast<float4*>(out + off) = o;
        }
    }
}

// ---------------- depthwise 3x3 fused with checkerboard squeeze ----------------
__global__ void dw_squeeze_kernel(const float* __restrict__ in,
                                  const float* __restrict__ wt,
                                  const float* __restrict__ bias,
                                  float* __restrict__ out, int anchor)
{
    int id = blockIdx.x * blockDim.x + threadIdx.x;
    if (id >= BB*CCH*NSQ) return;
    int j = id & (WHF-1);
    int i = (id >> 7) & (HH-1);
    int c = (id >> 15) & (CCH-1);
    int b = id >> 21;
    int x = 2*j + (anchor ? (1 - (i & 1)) : (i & 1));
    float w[9];
    #pragma unroll
    for (int t = 0; t < 9; t++) w[t] = __ldg(&wt[c*9 + t]);
    float acc = bias[c];
    const float* base = in + (size_t)(b*CCH + c) * HWW;
    #pragma unroll
    for (int dy = -1; dy <= 1; dy++) {
        int yy = i + dy;
        if (yy < 0 || yy >= HH) continue;
        #pragma unroll
        for (int dx = -1; dx <= 1; dx++) {
            int xx = x + dx;
            if (xx < 0 || xx >= WWD) continue;
            acc += w[(dy+1)*3 + (dx+1)] * base[yy*WWD + xx];
        }
    }
    out[id] = acc;
}

// ---------------- softmax over n per (b,c) row, in place ----------------
__global__ __launch_bounds__(512) void softmax_k_kernel(float* __restrict__ data)
{
    __shared__ float sm[16];
    float* ptr = data + (size_t)blockIdx.x * NSQ;
    int tid = threadIdx.x;

    float m = -1e30f;
    for (int idx = tid; idx < NSQ; idx += 512) m = fmaxf(m, ptr[idx]);
    #pragma unroll
    for (int o = 16; o; o >>= 1) m = fmaxf(m, __shfl_xor_sync(0xffffffffu, m, o));
    if ((tid & 31) == 0) sm[tid >> 5] = m;
    __syncthreads();
    if (tid < 32) {
        float t = (tid < 16) ? sm[tid] : -1e30f;
        #pragma unroll
        for (int o = 8; o; o >>= 1) t = fmaxf(t, __shfl_xor_sync(0xffffffffu, t, o));
        if (tid == 0) sm[0] = t;
    }
    __syncthreads();
    m = sm[0];
    __syncthreads();

    float s = 0.f;
    for (int idx = tid; idx < NSQ; idx += 512) s += expf(ptr[idx] - m);
    #pragma unroll
    for (int o = 16; o; o >>= 1) s += __shfl_xor_sync(0xffffffffu, s, o);
    if ((tid & 31) == 0) sm[tid >> 5] = s;
    __syncthreads();
    if (tid < 32) {
        float t = (tid < 16) ? sm[tid] : 0.f;
        #pragma unroll
        for (int o = 8; o; o >>= 1) t += __shfl_xor_sync(0xffffffffu, t, o);
        if (tid == 0) sm[0] = t;
    }
    __syncthreads();
    float inv = 1.f / sm[0];
    for (int idx = tid; idx < NSQ; idx += 512) ptr[idx] = expf(ptr[idx] - m) * inv;
}

// ---------------- ctx = k_sm @ v_s^T  (16x16 per (b,head)) ----------------
__global__ void ctx_zero_kernel() {
    int id = blockIdx.x * blockDim.x + threadIdx.x;
    if (id < BB*NHEADS*DDIM*DDIM) g_ctx[id] = 0.f;
}

__global__ __launch_bounds__(256) void ctx_kernel()
{
    __shared__ float ka[16][129];
    __shared__ float va[16][129];
    int bh = blockIdx.x;
    int chunk = blockIdx.y;
    int b = bh >> 2, h = bh & 3;
    int tid = threadIdx.x;
    int d = tid >> 4, e = tid & 15;
    const float* kbase = g_ks + (size_t)(b*CCH + h*16) * NSQ;
    const float* vbase = g_vs + (size_t)(b*CCH + h*16) * NSQ;
    float acc = 0.f;
    for (int sub = 0; sub < 8; sub++) {
        int n0 = chunk * 1024 + sub * 128;
        __syncthreads();
        #pragma unroll
        for (int q = tid; q < 2048; q += 256) {
            int r = q >> 7, t = q & 127;
            ka[r][t] = kbase[(size_t)r * NSQ + n0 + t];
            va[r][t] = vbase[(size_t)r * NSQ + n0 + t];
        }
        __syncthreads();
        #pragma unroll
        for (int t = 0; t < 128; t++) acc += ka[d][t] * va[e][t];
    }
    atomicAdd(&g_ctx[bh*256 + tid], acc);
}

// ---------------- q softmax(over d) + ctx apply -> SQUEEZED att ----------------
__global__ __launch_bounds__(256) void att_kernel()
{
    __shared__ float cs[16][17];
    int bh = blockIdx.y;
    int b = bh >> 2, h = bh & 3;
    int tid = threadIdx.x;
    int n = blockIdx.x * 256 + tid;
    cs[tid >> 4][tid & 15] = g_ctx[bh*256 + tid];
    __syncthreads();

    const float* qb = g_qs + (size_t)(b*CCH + h*16) * NSQ + n;
    float p[16];
    float m = -1e30f;
    #pragma unroll
    for (int d = 0; d < 16; d++) { p[d] = qb[(size_t)d * NSQ]; m = fmaxf(m, p[d]); }
    float s = 0.f;
    #pragma unroll
    for (int d = 0; d < 16; d++) { p[d] = expf(p[d] - m); s += p[d]; }
    float inv = 1.f / s;

    int i = n >> 7, j = n & 127;
    #pragma unroll
    for (int e = 0; e < 16; e++) {
        float a = 0.f;
        #pragma unroll
        for (int d = 0; d < 16; d++) a += cs[d][e] * p[d];
        a *= inv;
        // squeezed layout: att_s[b][c][i][j] = att value at x = 2j + (i&1)
        g_att[((size_t)(b*CCH + h*16 + e) * HH + i) * WHF + j] = a;
    }
}

// ---------------- 5x5 conv 64 -> 128, pad 2, checkerboard-sparse input ----------------
// Input is squeezed att: nonzero full-grid position (yy, xx) iff (yy+xx) even,
// value = att_s[yy][(xx - (yy&1))/2]. Only active taps computed (~half the FMAs),
// accumulated pairwise with fma.rn.f32x2 (outputs v and v+2 share taps).
__global__ __launch_bounds__(256) void conv5_kernel(
    const float* __restrict__ wt, const float* __restrict__ bias)
{
    __shared__ float  xs[8][68];     // squeezed rows with halo
    __shared__ float2 wsd[16*25];    // weights duplicated (w,w)
    int X0  = blockIdx.x * 128;
    int y0  = blockIdx.y * 4;
    int b   = blockIdx.z >> 3;
    int cot = blockIdx.z & 7;
    int tid = threadIdx.x;
    int cg  = tid & 3;               // 4 co each -> warp-uniform py below
    int px0 = ((tid >> 2) & 15) * 8; // 0..120
    int py  = tid >> 6;              // 0..3, uniform per warp
    int th  = px0 >> 1;
    int jb  = X0/2 - 1;

    // acc2[u][m]: m=0 -> (v0,v2), m=1 -> (v1,v3), m=2 -> (v4,v6), m=3 -> (v5,v7)
    u64 acc2[4][4];
    #pragma unroll
    for (int u = 0; u < 4; u++)
        #pragma unroll
        for (int m = 0; m < 4; m++) acc2[u][m] = 0ull;

    for (int ci = 0; ci < 64; ci++) {
        __syncthreads();
        const float* ib = g_att + (size_t)(b*CCH + ci) * NSQ;
        for (int q = tid; q < 544; q += 256) {
            int r = q / 68, t = q - r * 68;
            int yy = y0 + r - 2;
            int jj = jb + t;
            float v = 0.f;
            if (yy >= 0 && yy < HH && jj >= 0 && jj < WHF) v = ib[yy*WHF + jj];
            xs[r][t] = v;
        }
        for (int q = tid; q < 400; q += 256) {
            int co = q / 25, tap = q - co * 25;
            float wv = wt[((size_t)(cot*16 + co) * 64 + ci) * 25 + tap];
            wsd[co*25 + tap] = make_float2(wv, wv);
        }
        __syncthreads();

        #pragma unroll
        for (int dy = 0; dy < 5; dy++) {
            int r = py + dy;
            float4 a4 = *reinterpret_cast<const float4*>(&xs[r][th]);
            float4 b4 = *reinterpret_cast<const float4*>(&xs[r][th + 4]);
            float rv[8] = {a4.x,a4.y,a4.z,a4.w, b4.x,b4.y,b4.z,b4.w};
            u64 rp[5];
            #pragma unroll
            for (int t = 0; t < 5; t++) rp[t] = pk(rv[t], rv[t+1]);

            const u64* wrow = reinterpret_cast<const u64*>(wsd) + (cg*4)*25 + dy*5;
            if ((r & 1) == 0) {   // input-row parity 0: taps with (v+dx) even
                #pragma unroll
                for (int u = 0; u < 4; u++) {
                    const u64* wr = wrow + u*25;
                    // v even (pairs base 0,4), dx in {0,2,4}
                    #pragma unroll
                    for (int dx = 0; dx < 5; dx += 2) {
                        u64 w = wr[dx];
                        fma2(acc2[u][0], w, rp[dx>>1]);
                        fma2(acc2[u][2], w, rp[(dx>>1) + 2]);
                    }
                    // v odd (pairs base 1,5), dx in {1,3}
                    #pragma unroll
                    for (int dx = 1; dx < 5; dx += 2) {
                        u64 w = wr[dx];
                        fma2(acc2[u][1], w, rp[(1+dx)>>1]);
                        fma2(acc2[u][3], w, rp[(5+dx)>>1]);
                    }
                }
            } else {              // parity 1: taps with (v+dx) odd
                #pragma unroll
                for (int u = 0; u < 4; u++) {
                    const u64* wr = wrow + u*25;
                    // v even, dx in {1,3}
                    #pragma unroll
                    for (int dx = 1; dx < 5; dx += 2) {
                        u64 w = wr[dx];
                        fma2(acc2[u][0], w, rp[(dx-1)>>1]);
                        fma2(acc2[u][2], w, rp[(dx+3)>>1]);
                    }
                    // v odd, dx in {0,2,4}
                    #pragma unroll
                    for (int dx = 0; dx < 5; dx += 2) {
                        u64 w = wr[dx];
                        fma2(acc2[u][1], w, rp[dx>>1]);
                        fma2(acc2[u][3], w, rp[(dx>>1) + 2]);
                    }
                }
            }
        }
    }

    #pragma unroll
    for (int u = 0; u < 4; u++) {
        int co = cot*16 + cg*4 + u;
        float bb = bias[co];
        float2 q0 = upk(acc2[u][0]);  // v0, v2
        float2 q1 = upk(acc2[u][1]);  // v1, v3
        float2 q2 = upk(acc2[u][2]);  // v4, v6
        float2 q3 = upk(acc2[u][3]);  // v5, v7
        size_t base = ((size_t)(b*C2 + co) * HH + (y0 + py)) * WWD + X0 + px0;
        float4 o0 = make_float4(q0.x + bb, q1.x + bb, q0.y + bb, q1.y + bb);
        float4 o1 = make_float4(q2.x + bb, q3.x + bb, q2.y + bb, q3.y + bb);
        *reinterpret_cast<float4*>(&g_attn[base])     = o0;
        *reinterpret_cast<float4*>(&g_attn[base + 4]) = o1;
    }
}

// ---------------- depthwise 3x3 (256 ch) + gelu ----------------
__global__ void dw_gelu_kernel(const float* __restrict__ in,
                               const float* __restrict__ wt,
                               const float* __restrict__ bias,
                               float* __restrict__ out)
{
    int id = blockIdx.x * blockDim.x + threadIdx.x;
    if (id >= BB*C4*HWW) return;
    int j = id & 255;
    int i = (id >> 8) & 255;
    int c = (id >> 16) & 255;
    int b = id >> 24;
    float w[9];
    #pragma unroll
    for (int t = 0; t < 9; t++) w[t] = __ldg(&wt[c*9 + t]);
    float acc = bias[c];
    const float* base = in + (size_t)(b*C4 + c) * HWW;
    #pragma unroll
    for (int dy = -1; dy <= 1; dy++) {
        int yy = i + dy;
        if (yy < 0 || yy >= HH) continue;
        #pragma unroll
        for (int dx = -1; dx <= 1; dx++) {
            int xx = j + dx;
            if (xx < 0 || xx >= WWD) continue;
            acc += w[(dy+1)*3 + (dx+1)] * base[yy*WWD + xx];
        }
    }
    out[id] = gelu_f(acc);
}

// ---------------- launch ----------------
extern "C" void kernel_launch(void* const* d_in, const int* in_sizes, int n_in,
                              void* d_out, int out_size)
{
    const float* x1   = (const float*)d_in[0];
    const float* x2   = (const float*)d_in[1];
    const float* q1_w = (const float*)d_in[2];
    const float* q1_b = (const float*)d_in[3];
    const float* q2_w = (const float*)d_in[4];
    const float* q2_b = (const float*)d_in[5];
    const float* k1_w = (const float*)d_in[6];
    const float* k1_b = (const float*)d_in[7];
    const float* k2_w = (const float*)d_in[8];
    const float* k2_b = (const float*)d_in[9];
    const float* v1_w = (const float*)d_in[10];
    const float* v1_b = (const float*)d_in[11];
    const float* v2_w = (const float*)d_in[12];
    const float* v2_b = (const float*)d_in[13];
    const float* r_w  = (const float*)d_in[14];
    const float* r_b  = (const float*)d_in[15];
    const float* m1_w = (const float*)d_in[16];
    const float* m1_b = (const float*)d_in[17];
    const float* m2_w = (const float*)d_in[18];
    const float* m2_b = (const float*)d_in[19];
    const float* m3_w = (const float*)d_in[20];
    const float* m3_b = (const float*)d_in[21];
    float* out = (float*)d_out;

    float *p_q1, *p_k1, *p_v1, *p_qs, *p_ks, *p_vs, *p_attn, *p_m1, *p_m2;
    cudaGetSymbolAddress((void**)&p_q1, g_q1);
    cudaGetSymbolAddress((void**)&p_k1, g_k1);
    cudaGetSymbolAddress((void**)&p_v1, g_v1);
    cudaGetSymbolAddress((void**)&p_qs, g_qs);
    cudaGetSymbolAddress((void**)&p_ks, g_ks);
    cudaGetSymbolAddress((void**)&p_vs, g_vs);
    cudaGetSymbolAddress((void**)&p_attn, g_attn);
    cudaGetSymbolAddress((void**)&p_m1, g_m1);
    cudaGetSymbolAddress((void**)&p_m2, g_m2);

    dim3 g1(HWW/128, 1, BB);
    conv1x1_kernel<64,64,0,1><<<g1, 256>>>(x1, q1_w, q1_b, nullptr, p_q1);
    conv1x1_kernel<64,64,0,2><<<g1, 256>>>(x1, k1_w, k1_b, nullptr, p_k1);
    conv1x1_kernel<64,64,0,0><<<g1, 256>>>(x2, v1_w, v1_b, nullptr, p_v1);

    int ndw = BB*CCH*NSQ;
    dw_squeeze_kernel<<<ndw/256, 256>>>(p_q1, q2_w, q2_b, p_qs, 0);
    dw_squeeze_kernel<<<ndw/256, 256>>>(p_k1, k2_w, k2_b, p_ks, 1);
    dw_squeeze_kernel<<<ndw/256, 256>>>(p_v1, v2_w, v2_b, p_vs, 1);

    softmax_k_kernel<<<BB*CCH, 512>>>(p_ks);

    ctx_zero_kernel<<<16, 256>>>();
    ctx_kernel<<<dim3(BB*NHEADS, 32), 256>>>();

    att_kernel<<<dim3(NSQ/256, BB*NHEADS), 256>>>();

    conv5_kernel<<<dim3(2, 64, 32), 256>>>(r_w, r_b);

    conv1x1_kernel<128,256,1,0><<<dim3(HWW/128, 4, BB), 256>>>(p_attn, m1_w, m1_b, nullptr, p_m1);

    dw_gelu_kernel<<<(BB*C4*HWW)/256, 256>>>(p_m1, m2_w, m2_b, p_m2);

    conv1x1_kernel<256,128,2,0><<<dim3(HWW/128, 2, BB), 256>>>(p_m2, m3_w, m3_b, p_attn, out);
}